// round 2
// baseline (speedup 1.0000x reference)
#include <cuda_runtime.h>
#include <math.h>

// Problem dims (fixed by the reference)
#define S_LEN 2048
#define B_SZ  64
#define I_SZ  512
#define H_SZ  512
#define G_SZ  2048            // 4*H
#define M1    (S_LEN * B_SZ)  // 131072

// ---------------- scratch (static device globals; no cudaMalloc allowed) ---
__device__ float g_xw[(size_t)M1 * G_SZ];     // [S*B, 4H] input projection (~1GB)
__device__ float g_h[2][B_SZ * H_SZ];         // double-buffered hidden state
#define NBLK 128
__device__ int   g_flags[NBLK * 32];          // per-block step flags, 128B padded

// =====================================================================
// Phase 1: xW = x @ W + bias   (M=131072, K=512, N=2048) fp32 SGEMM
// 128x128 tile, BK=8, 8x8 per-thread micro-tile, 256 threads
// =====================================================================
#define BM 128
#define BN 128
#define BKK 8

__global__ __launch_bounds__(256) void gemm_xw_kernel(
    const float* __restrict__ A,     // x  [M1, I]
    const float* __restrict__ Wm,    // W  [I, G]
    const float* __restrict__ bias,  // [G]
    float* __restrict__ C)           // g_xw [M1, G]
{
    __shared__ float As[BKK][BM];
    __shared__ float Bs[BKK][BN];

    const int bx = blockIdx.x;   // N tile: 0..15
    const int by = blockIdx.y;   // M tile: 0..1023
    const int tid = threadIdx.x;

    const int arow = tid >> 1;          // 0..127
    const int acol = (tid & 1) << 2;    // 0,4
    const int brow = tid >> 5;          // 0..7
    const int bcol = (tid & 31) << 2;   // 0..124

    const float* Ag = A + (size_t)(by * BM + arow) * I_SZ + acol;
    const float* Bg = Wm + (size_t)brow * G_SZ + bx * BN + bcol;

    const int tr = (tid >> 4) << 3;
    const int tc = (tid & 15) << 3;

    float acc[8][8];
#pragma unroll
    for (int i = 0; i < 8; i++)
#pragma unroll
        for (int j = 0; j < 8; j++) acc[i][j] = 0.f;

    for (int k0 = 0; k0 < I_SZ; k0 += BKK) {
        float4 a4 = *(const float4*)(Ag + k0);
        As[acol + 0][arow] = a4.x;
        As[acol + 1][arow] = a4.y;
        As[acol + 2][arow] = a4.z;
        As[acol + 3][arow] = a4.w;
        *(float4*)&Bs[brow][bcol] = *(const float4*)(Bg + (size_t)k0 * G_SZ);
        __syncthreads();

#pragma unroll
        for (int k = 0; k < BKK; k++) {
            float ar[8], br[8];
#pragma unroll
            for (int i = 0; i < 8; i++) ar[i] = As[k][tr + i];
#pragma unroll
            for (int j = 0; j < 8; j++) br[j] = Bs[k][tc + j];
#pragma unroll
            for (int i = 0; i < 8; i++)
#pragma unroll
                for (int j = 0; j < 8; j++) acc[i][j] += ar[i] * br[j];
        }
        __syncthreads();
    }

    float bl[8];
#pragma unroll
    for (int j = 0; j < 8; j++) bl[j] = bias[bx * BN + tc + j];

#pragma unroll
    for (int i = 0; i < 8; i++) {
        float* cp = C + (size_t)(by * BM + tr + i) * G_SZ + bx * BN + tc;
#pragma unroll
        for (int j = 0; j < 8; j += 4) {
            float4 v;
            v.x = acc[i][j + 0] + bl[j + 0];
            v.y = acc[i][j + 1] + bl[j + 1];
            v.z = acc[i][j + 2] + bl[j + 2];
            v.w = acc[i][j + 3] + bl[j + 3];
            *(float4*)(cp + j) = v;
        }
    }
}

// =====================================================================
// reset kernel: zero flags + initial hidden state (called each launch)
// =====================================================================
__global__ void reset_kernel() {
    int tid = threadIdx.x + blockIdx.x * blockDim.x;
    for (int i = tid; i < NBLK * 32; i += blockDim.x * gridDim.x)
        g_flags[i] = 0;
    for (int i = tid; i < B_SZ * H_SZ; i += blockDim.x * gridDim.x)
        g_h[0][i] = 0.f;
}

// =====================================================================
// Phase 2: persistent recurrence kernel
// 128 blocks (<=148 SMs: all co-resident, 1 CTA/SM by smem), 256 threads.
// Block bk owns hidden cols [bk*4, bk*4+4) => its 16 U columns stay
// resident in SMEM for all 2048 steps.
// Distributed flag barrier: each block publishes its step to its own
// padded slot; 128 threads spin on one slot each (no atomic serialization).
// =====================================================================
#define HCPB 4
#define T2   256
#define USTR 516                       // padded row stride (bank spread, %4==0)
#define US_OFF 0                       // 16*516 floats
#define HS_OFF (16 * USTR)             // 64*516 floats
#define GS_OFF (HS_OFF + 64 * USTR)    // 64*16
#define CS_OFF (GS_OFF + 64 * 16)      // 64*4
#define SMEM_FLOATS (CS_OFF + 64 * HCPB)

__global__ __launch_bounds__(T2, 1) void lstm_rec_kernel(
    const float* __restrict__ xw,    // g_xw [S, B, G]
    const float* __restrict__ U,     // [H, G] row-major
    float* __restrict__ out_seq,     // [S, B, H]
    float* __restrict__ out_h,       // [B, H] or null
    float* __restrict__ out_c)       // [B, H] or null
{
    extern __shared__ float sm[];
    const int tid = threadIdx.x;
    const int bk  = blockIdx.x;
    const int hc0 = bk * HCPB;

    // ---- load U slice into SMEM (persists across all timesteps) ----
    for (int i = tid; i < 16 * H_SZ; i += T2) {
        int lc = i / H_SZ, k = i - lc * H_SZ;
        int q = lc >> 2, j = lc & 3;
        sm[US_OFF + lc * USTR + k] = U[(size_t)k * G_SZ + q * H_SZ + hc0 + j];
    }
    // ---- init c state ----
    sm[CS_OFF + tid] = 0.f;   // 256 == 64*HCPB
    __syncthreads();

    const int c    = tid & 15;        // local gate-col 0..15
    const int gq   = c >> 2;
    const int gj   = c & 3;
    const int gcol = gq * H_SZ + hc0 + gj;
    const int bgrp = tid >> 4;        // 0..15

    const int eb = tid >> 2;          // elementwise: batch
    const int ej = tid & 3;           // elementwise: hidden-col-in-block

    volatile int* flags = (volatile int*)g_flags;

    for (int t = 0; t < S_LEN; t++) {
        // prefetch xw row entries (independent of barrier / h)
        const float* xwrow = xw + (size_t)t * (B_SZ * G_SZ);
        float a0 = xwrow[(size_t)(bgrp +  0) * G_SZ + gcol];
        float a1 = xwrow[(size_t)(bgrp + 16) * G_SZ + gcol];
        float a2 = xwrow[(size_t)(bgrp + 32) * G_SZ + gcol];
        float a3 = xwrow[(size_t)(bgrp + 48) * G_SZ + gcol];

        // ---- load h(t) into SMEM (L2-only loads: other SMs wrote it) ----
        const float* hsrc = g_h[t & 1];
        for (int i = tid * 4; i < B_SZ * H_SZ; i += T2 * 4) {
            float4 v = __ldcg((const float4*)(hsrc + i));
            int b = i >> 9, k = i & 511;
            *(float4*)&sm[HS_OFF + b * USTR + k] = v;
        }
        __syncthreads();

        // ---- gates = xw + h @ U_slice : thread does 4 batches x 1 col ----
        float acc0 = a0, acc1 = a1, acc2 = a2, acc3 = a3;
        const float* up  = &sm[US_OFF + c * USTR];
        const float* h0p = &sm[HS_OFF + (bgrp +  0) * USTR];
        const float* h1p = &sm[HS_OFF + (bgrp + 16) * USTR];
        const float* h2p = &sm[HS_OFF + (bgrp + 32) * USTR];
        const float* h3p = &sm[HS_OFF + (bgrp + 48) * USTR];
#pragma unroll 4
        for (int k = 0; k < H_SZ; k += 4) {
            float4 u  = *(const float4*)(up  + k);
            float4 v0 = *(const float4*)(h0p + k);
            float4 v1 = *(const float4*)(h1p + k);
            float4 v2 = *(const float4*)(h2p + k);
            float4 v3 = *(const float4*)(h3p + k);
            acc0 += v0.x * u.x; acc0 += v0.y * u.y; acc0 += v0.z * u.z; acc0 += v0.w * u.w;
            acc1 += v1.x * u.x; acc1 += v1.y * u.y; acc1 += v1.z * u.z; acc1 += v1.w * u.w;
            acc2 += v2.x * u.x; acc2 += v2.y * u.y; acc2 += v2.z * u.z; acc2 += v2.w * u.w;
            acc3 += v3.x * u.x; acc3 += v3.y * u.y; acc3 += v3.z * u.z; acc3 += v3.w * u.w;
        }
        sm[GS_OFF + (bgrp +  0) * 16 + c] = acc0;
        sm[GS_OFF + (bgrp + 16) * 16 + c] = acc1;
        sm[GS_OFF + (bgrp + 32) * 16 + c] = acc2;
        sm[GS_OFF + (bgrp + 48) * 16 + c] = acc3;
        __syncthreads();

        // ---- elementwise: one thread per (batch, hidden-col-in-block) ----
        float gi = sm[GS_OFF + eb * 16 +  0 + ej];
        float gf = sm[GS_OFF + eb * 16 +  4 + ej];
        float gg = sm[GS_OFF + eb * 16 +  8 + ej];
        float go = sm[GS_OFF + eb * 16 + 12 + ej];
        float it = 1.f / (1.f + __expf(-gi));
        float ft = 1.f / (1.f + __expf(-gf));
        float gt = tanhf(gg);
        float ot = 1.f / (1.f + __expf(-go));
        float cold = sm[CS_OFF + tid];
        float cnew = ft * cold + it * gt;
        sm[CS_OFF + tid] = cnew;
        float hnew = ot * tanhf(cnew);

        int hidx = eb * H_SZ + hc0 + ej;
        g_h[(t + 1) & 1][hidx] = hnew;
        out_seq[(size_t)t * (B_SZ * H_SZ) + hidx] = hnew;
        if (t == S_LEN - 1) {
            if (out_h) out_h[hidx] = hnew;
            if (out_c) out_c[hidx] = cnew;
        }

        // ---- distributed grid barrier (skip after the last step) ----
        if (t < S_LEN - 1) {
            __threadfence();          // each thread publishes its h stores
            __syncthreads();          // order tid0's flag store after all fences
            if (tid == 0)
                flags[bk * 32] = t + 1;        // padded slot, plain parallel store
            if (tid < NBLK) {
                while (flags[tid * 32] < t + 1) { }   // one slot per thread
            }
            __threadfence();          // acquire: order subsequent h reads
            __syncthreads();
        }
    }
}

// =====================================================================
// launch
// =====================================================================
extern "C" void kernel_launch(void* const* d_in, const int* in_sizes, int n_in,
                              void* d_out, int out_size) {
    const float* x    = (const float*)d_in[0];   // [S,B,I]
    const float* W    = (const float*)d_in[1];   // [I,4H]
    const float* U    = (const float*)d_in[2];   // [H,4H]
    const float* bias = (const float*)d_in[3];   // [4H]
    float* out = (float*)d_out;

    float* xw_ptr; cudaGetSymbolAddress((void**)&xw_ptr, g_xw);

    const long long seq_elems = (long long)S_LEN * B_SZ * H_SZ;
    float* out_h = nullptr;
    float* out_c = nullptr;
    if ((long long)out_size >= seq_elems + (long long)B_SZ * H_SZ)
        out_h = out + seq_elems;
    if ((long long)out_size >= seq_elems + 2LL * B_SZ * H_SZ)
        out_c = out + seq_elems + (long long)B_SZ * H_SZ;

    // Phase 1: input projection
    dim3 g1(G_SZ / BN, M1 / BM);        // (16, 1024)
    gemm_xw_kernel<<<g1, 256>>>(x, W, bias, xw_ptr);

    // reset flags + h0
    reset_kernel<<<32, 256>>>();

    // Phase 2: persistent recurrence
    static const int smem_bytes = SMEM_FLOATS * (int)sizeof(float);
    cudaFuncSetAttribute((const void*)lstm_rec_kernel,
                         cudaFuncAttributeMaxDynamicSharedMemorySize, smem_bytes);
    lstm_rec_kernel<<<NBLK, T2, smem_bytes>>>(xw_ptr, U, out, out_h, out_c);
}